// round 9
// baseline (speedup 1.0000x reference)
#include <cuda_runtime.h>
#include <cstdint>

// ItemCodeDPQ: out[b,s,m*16+d] = centroids[m, clamp(item_codes[input_ids[b,s], m],0,255), d]
//              zeroed where input_ids[b,s] == 0.  input_ids arrive as int32.
//
// R9: two-kernel split to break the 3-deep dependent load chain.
//  k1: resolve id -> row index (sub*256+code, high bit = zero-token) into a
//      packed __device__ scratch. Grid-parallel, unbounded MLP.
//  k2: coalesced rowidx read -> L1-resident centroid gather -> streaming store.

#define MAX_TOK (1024 * 200)
__device__ int g_rowidx[MAX_TOK * 8];   // 6.55 MB scratch

// ---------------- kernel 1: code resolve ----------------
__global__ void __launch_bounds__(256)
resolve_codes_kernel(const int* __restrict__ input_ids,
                     const int* __restrict__ item_codes,
                     int nwork)                     // nwork = ntok*8
{
    unsigned wi = blockIdx.x * 256u + threadIdx.x;
    if (wi >= (unsigned)nwork) return;
    const unsigned sub = wi & 7u;
    const unsigned id  = (unsigned)__ldg(&input_ids[wi >> 3]);   // 8 lanes share
    int code = __ldg(&item_codes[id * 8u + sub]);
    code = min(max(code, 0), 255);
    int rid = (int)(sub * 256u + (unsigned)code);
    if (id == 0u) rid |= (int)0x80000000;
    g_rowidx[wi] = rid;
}

// ---------------- kernel 2: gather + store ----------------
__global__ void __launch_bounds__(256)
gather_store_kernel(const float4* __restrict__ centroids4,
                    float4* __restrict__ out4,
                    int ntok)
{
    const unsigned lane = threadIdx.x & 31u;
    const unsigned sub  = lane >> 2;          // 0..7
    const unsigned part = lane & 3u;          // 0..3

    const unsigned warp = (blockIdx.x * blockDim.x + threadIdx.x) >> 5;
    const unsigned t0   = warp * 8u;
    if (t0 >= (unsigned)ntok) return;         // ntok divisible by 8

    // stage 8 row indices (coalesced-ish: 1 sector per token, L2-fresh)
    int r[8];
    #pragma unroll
    for (int j = 0; j < 8; j++)
        r[j] = g_rowidx[(t0 + (unsigned)j) * 8u + sub];

    #pragma unroll
    for (int j = 0; j < 8; j++) {
        const unsigned row = (unsigned)r[j] & 0x7fffffffu;
        float4 v = __ldg(&centroids4[row * 4u + part]);
        if (r[j] < 0) v = make_float4(0.f, 0.f, 0.f, 0.f);
        __stcs(&out4[(t0 + (unsigned)j) * 32u + lane], v);
    }
}

extern "C" void kernel_launch(void* const* d_in, const int* in_sizes, int n_in,
                              void* d_out, int out_size)
{
    const int*    input_ids  = (const int*)d_in[0];     // (1024,200) int32
    const int*    item_codes = (const int*)d_in[1];     // (1e6, 8) int32
    const float4* centroids  = (const float4*)d_in[2];  // (8,256,16) fp32
    float4*       out        = (float4*)d_out;          // (1024,200,128) fp32

    const int ntok  = in_sizes[0];   // 204800
    const int nwork = ntok * 8;

    int ctas1 = (nwork + 255) / 256;
    resolve_codes_kernel<<<ctas1, 256>>>(input_ids, item_codes, nwork);

    // 8 tokens per warp, 8 warps per 256-thread CTA => 64 tokens per CTA
    int warps = (ntok + 7) / 8;
    int ctas2 = (warps + 7) / 8;
    gather_store_kernel<<<ctas2, 256>>>(centroids, out, ntok);
}

// round 10
// speedup vs baseline: 1.1346x; 1.1346x over previous
#include <cuda_runtime.h>
#include <cstdint>

// ItemCodeDPQ: out[b,s,m*16+d] = centroids[m, clamp(item_codes[input_ids[b,s], m],0,255), d]
//              zeroed where input_ids[b,s] == 0.  input_ids arrive as int32.
//
// R10: smem-staged centroid table (128KB, no L1 gather-replay tax; smem
// crossbar runs parallel to the L1tex store path) + the R8 phase-split
// 8-token batches, but at 1024 threads/CTA (32 warps/SM) so the LSU stays
// fed. Grid-stride over 8-token chunks; shuffle-free; __stcs stores.

#define CENT_F4 8192   // 8*256*16 floats / 4 = 131072 bytes

__global__ void __launch_bounds__(1024, 1)
itemcode_dpq_kernel(const int* __restrict__ input_ids,
                    const int* __restrict__ item_codes,
                    const float4* __restrict__ centroids4,
                    float4* __restrict__ out4,
                    int ntok)
{
    extern __shared__ float4 s_cent[];   // full centroid table

    // cooperative table load: 8 float4 per thread
    #pragma unroll
    for (int i = threadIdx.x; i < CENT_F4; i += 1024)
        s_cent[i] = centroids4[i];
    __syncthreads();

    const unsigned lane = threadIdx.x & 31u;
    const unsigned sub  = lane >> 2;          // 0..7 : sub-codebook this lane serves
    const unsigned part = lane & 3u;          // 0..3 : float4 within 16-float sub-emb

    const unsigned warp   = (blockIdx.x * 1024u + threadIdx.x) >> 5;
    const unsigned nwarp  = gridDim.x * 32u;
    const unsigned nchunk = (unsigned)ntok >> 3;      // ntok divisible by 8

    for (unsigned ch = warp; ch < nchunk; ch += nwarp) {
        const unsigned t0 = ch * 8u;

        // ---- Phase A: 8 independent id -> code chains (stage code ints) ----
        int c[8];
        unsigned zmask = 0u;
        #pragma unroll
        for (int j = 0; j < 8; j++) {
            const unsigned id = (unsigned)__ldg(&input_ids[t0 + (unsigned)j]);
            c[j] = __ldg(&item_codes[id * 8u + sub]);   // 1 sector/warp/token
            zmask |= (id == 0u) ? (1u << j) : 0u;
        }

        // ---- Phase B: 8 smem gathers (no replay tax) -> streaming stores ----
        #pragma unroll
        for (int j = 0; j < 8; j++) {
            const unsigned code = (unsigned)min(max(c[j], 0), 255);
            float4 v = s_cent[(sub * 256u + code) * 4u + part];
            if ((zmask >> j) & 1u) v = make_float4(0.f, 0.f, 0.f, 0.f);
            __stcs(&out4[(t0 + (unsigned)j) * 32u + lane], v);
        }
    }
}

extern "C" void kernel_launch(void* const* d_in, const int* in_sizes, int n_in,
                              void* d_out, int out_size)
{
    const int*    input_ids  = (const int*)d_in[0];     // (1024,200) int32
    const int*    item_codes = (const int*)d_in[1];     // (1e6, 8) int32
    const float4* centroids  = (const float4*)d_in[2];  // (8,256,16) fp32
    float4*       out        = (float4*)d_out;          // (1024,200,128) fp32

    const int ntok = in_sizes[0];   // 204800

    cudaFuncSetAttribute(itemcode_dpq_kernel,
                         cudaFuncAttributeMaxDynamicSharedMemorySize, 131072);

    int nsm = 148;
    cudaDeviceGetAttribute(&nsm, cudaDevAttrMultiProcessorCount, 0);

    itemcode_dpq_kernel<<<nsm, 1024, 131072>>>(input_ids, item_codes, centroids,
                                               out, ntok);
}